// round 2
// baseline (speedup 1.0000x reference)
#include <cuda_runtime.h>
#include <math.h>
#include <float.h>
#include <stdint.h>

// Problem constants (CTCLoss_30047591203274): predicts [B,T,C] f32,
// labels [B,L] i32 (values in [1,C)), label_lengths [B] i32 in [1,L].
constexpr int B = 128;
constexpr int T = 128;
constexpr int C = 6625;
constexpr int L = 25;
constexpr int S = 2 * L + 1;   // 51 extended states
constexpr int NE = L + 1;      // emit slots per (b,t): blank + L labels
constexpr float NEGV = -1e30f; // matches reference NEG

// Scratch (static device globals; no allocation allowed)
__device__ float g_emit[(size_t)B * T * NE]; // emit[b][t][j] = logit(cls_j) - lse
__device__ float g_partial[B];               // loss_b / len_b

// ---------------------------------------------------------------------------
// Kernel 1: per (b,t) row — logsumexp over C + gather 26 classes.
// One block per row, 256 threads. Each thread register-caches its 26 strided
// elements (pad = -FLT_MAX so pads are identity for max and contribute 0 to
// sum-exp). Row is read from DRAM exactly once.
// ---------------------------------------------------------------------------
__global__ __launch_bounds__(256) void k_lse_gather(
    const float* __restrict__ pred, const int* __restrict__ labels)
{
    const int bt = blockIdx.x;           // 0 .. B*T-1
    const int b  = bt / T;
    const float* row = pred + (size_t)bt * C;
    const int tid = threadIdx.x;

    constexpr int PER = (C + 255) / 256; // 26
    float v[PER];
#pragma unroll
    for (int k = 0; k < PER; k++) {
        int idx = tid + k * 256;
        v[k] = (idx < C) ? __ldg(row + idx) : -FLT_MAX;
    }

    // local max
    float m = v[0];
#pragma unroll
    for (int k = 1; k < PER; k++) m = fmaxf(m, v[k]);
    // warp reduce max
#pragma unroll
    for (int o = 16; o > 0; o >>= 1)
        m = fmaxf(m, __shfl_xor_sync(0xffffffffu, m, o));

    __shared__ float sw[8];
    __shared__ float sbc;
    if ((tid & 31) == 0) sw[tid >> 5] = m;
    __syncthreads();                               // sync1
    if (tid == 0) {
        float mm = sw[0];
#pragma unroll
        for (int w = 1; w < 8; w++) mm = fmaxf(mm, sw[w]);
        sbc = mm;
    }
    __syncthreads();                               // sync2
    const float M = sbc;

    // local sum of exp
    float s = 0.f;
#pragma unroll
    for (int k = 0; k < PER; k++) s += __expf(v[k] - M);
#pragma unroll
    for (int o = 16; o > 0; o >>= 1)
        s += __shfl_xor_sync(0xffffffffu, s, o);

    __syncthreads();                               // sync3 (protect sw/sbc reuse)
    if ((tid & 31) == 0) sw[tid >> 5] = s;
    __syncthreads();                               // sync4
    if (tid == 0) {
        float tot = 0.f;
#pragma unroll
        for (int w = 0; w < 8; w++) tot += sw[w];
        sbc = M + __logf(tot);
    }
    __syncthreads();                               // sync5
    const float lse = sbc;

    if (tid < NE) {
        int cls = (tid == 0) ? 0 : labels[b * L + tid - 1];
        g_emit[(size_t)bt * NE + tid] = row[cls] - lse;
    }
}

// ---------------------------------------------------------------------------
// Kernel 2: CTC alpha recursion. One block per batch element, 64 threads
// (one state per thread, 51 active). Full emit table for this batch element
// staged into SMEM; double-buffered alpha; one barrier per timestep.
// ---------------------------------------------------------------------------
__global__ __launch_bounds__(64) void k_ctc_dp(
    const int* __restrict__ labels, const int* __restrict__ lens)
{
    const int b = blockIdx.x;
    const int tid = threadIdx.x;

    __shared__ float se[T * NE];       // 13312 B
    __shared__ float A[2][S + 1];
    __shared__ int lab[L];

    for (int i = tid; i < T * NE; i += 64)
        se[i] = g_emit[(size_t)b * T * NE + i];
    if (tid < L) lab[tid] = labels[b * L + tid];
    __syncthreads();

    const int s = tid;
    const bool act = (s < S);
    int j = 0;
    bool skip = false;
    if (act) {
        j = (s & 1) ? (s >> 1) + 1 : 0;          // emit slot for this state
        if ((s & 1) && s >= 3)
            skip = (lab[s >> 1] != lab[(s >> 1) - 1]);
    }

    if (act) {
        float a0 = (s == 0) ? se[0] : (s == 1) ? se[1] : NEGV;
        A[0][s] = a0;
    }
    __syncthreads();

    int cur = 0;
    for (int t = 1; t < T; t++) {
        if (act) {
            float a0 = A[cur][s];
            float a1 = (s >= 1) ? A[cur][s - 1] : NEGV;
            float a2 = skip ? A[cur][s - 2] : NEGV;
            float mm = fmaxf(a0, fmaxf(a1, a2));
            float val = mm
                + logf(expf(a0 - mm) + expf(a1 - mm) + expf(a2 - mm))
                + se[t * NE + j];
            A[cur ^ 1][s] = val;
        }
        __syncthreads();
        cur ^= 1;
    }

    if (tid == 0) {
        int len = lens[b];
        float x = A[cur][2 * len];
        float y = A[cur][2 * len - 1];
        float mm = fmaxf(x, y);
        float ll = mm + logf(expf(x - mm) + expf(y - mm));
        float loss = -ll;
        if (loss > 1e29f) loss = 0.f;              // zero_infinity
        g_partial[b] = loss / (float)len;
    }
}

// ---------------------------------------------------------------------------
// Kernel 3: final scalar reduce: out = sum_b(partial_b) / (B*B)
// ---------------------------------------------------------------------------
__global__ __launch_bounds__(128) void k_final(float* __restrict__ out)
{
    const int tid = threadIdx.x; // 128 threads
    float v = g_partial[tid];
#pragma unroll
    for (int o = 16; o > 0; o >>= 1)
        v += __shfl_xor_sync(0xffffffffu, v, o);
    __shared__ float sw[4];
    if ((tid & 31) == 0) sw[tid >> 5] = v;
    __syncthreads();
    if (tid == 0)
        out[0] = (sw[0] + sw[1] + sw[2] + sw[3]) / ((float)B * (float)B);
}

// ---------------------------------------------------------------------------
extern "C" void kernel_launch(void* const* d_in, const int* in_sizes, int n_in,
                              void* d_out, int out_size)
{
    const float* pred   = (const float*)d_in[0];
    const int*   labels = (const int*)d_in[1];
    const int*   lens   = (const int*)d_in[2];
    float*       out    = (float*)d_out;

    k_lse_gather<<<B * T, 256>>>(pred, labels);
    k_ctc_dp<<<B, 64>>>(labels, lens);
    k_final<<<1, 128>>>(out);
}